// round 1
// baseline (speedup 1.0000x reference)
#include <cuda_runtime.h>
#include <cuda_bf16.h>

// InterpNet fused MLP over gathered edge features.
// x = [latents[col], pos_target[row]-pos_source[col]]  (E x 259)
// x = x@W_in + b_in ; x = relu(x)@W1 + b1 ; x = relu(x)@W2 + b2 ; out = (x@W_out + b_out)[:,0]
//
// One CTA per 64-edge tile. Activations stay in SMEM across all layers.
// Weight K-tiles staged in SMEM. 4x16 register blocking, fp32 FFMA.

#define TM      64      // edges per CTA
#define THREADS 256
#define KT      16      // K tile rows staged in smem
#define LDIM    256
#define APAD    272     // A row stride in floats (>= 259 padded, room for K=259 tile overrun)

// smem floats: A[64][272] + Wt[16][256] + col[64(as int)]
#define SMEM_FLOATS (TM*APAD + KT*LDIM + TM)
#define SMEM_BYTES  (SMEM_FLOATS * 4)

template<int K, bool RELU>
__device__ __forceinline__ void dense256(float* __restrict__ A, float* __restrict__ Wt,
                                         const float* __restrict__ W,
                                         const float* __restrict__ b,
                                         int tid)
{
    const int tx = tid & 15;   // column group: cols [tx*16, tx*16+16)
    const int ty = tid >> 4;   // row group:    rows [ty*4,  ty*4+4)

    float acc[4][16];
    {
        const float4* b4 = reinterpret_cast<const float4*>(b);
        #pragma unroll
        for (int c4 = 0; c4 < 4; c4++) {
            float4 bb = b4[tx * 4 + c4];
            #pragma unroll
            for (int r = 0; r < 4; r++) {
                acc[r][c4*4+0] = bb.x; acc[r][c4*4+1] = bb.y;
                acc[r][c4*4+2] = bb.z; acc[r][c4*4+3] = bb.w;
            }
        }
    }

    const int NTILES = (K + KT - 1) / KT;
    #pragma unroll 1
    for (int t = 0; t < NTILES; t++) {
        const int k0 = t * KT;
        // stage W[k0:k0+16, 0:256] -> Wt, zero-fill past K
        #pragma unroll
        for (int i = 0; i < KT; i++) {
            int k = k0 + i;
            Wt[i * LDIM + tid] = (k < K) ? W[k * LDIM + tid] : 0.0f;
        }
        __syncthreads();

        #pragma unroll
        for (int kk = 0; kk < KT; kk++) {
            const int k = k0 + kk;
            float a0 = A[(ty*4+0)*APAD + k];
            float a1 = A[(ty*4+1)*APAD + k];
            float a2 = A[(ty*4+2)*APAD + k];
            float a3 = A[(ty*4+3)*APAD + k];
            const float4* wrow = reinterpret_cast<const float4*>(Wt + kk * LDIM);
            #pragma unroll
            for (int c4 = 0; c4 < 4; c4++) {
                float4 w = wrow[tx * 4 + c4];
                acc[0][c4*4+0] += a0 * w.x; acc[0][c4*4+1] += a0 * w.y;
                acc[0][c4*4+2] += a0 * w.z; acc[0][c4*4+3] += a0 * w.w;
                acc[1][c4*4+0] += a1 * w.x; acc[1][c4*4+1] += a1 * w.y;
                acc[1][c4*4+2] += a1 * w.z; acc[1][c4*4+3] += a1 * w.w;
                acc[2][c4*4+0] += a2 * w.x; acc[2][c4*4+1] += a2 * w.y;
                acc[2][c4*4+2] += a2 * w.z; acc[2][c4*4+3] += a2 * w.w;
                acc[3][c4*4+0] += a3 * w.x; acc[3][c4*4+1] += a3 * w.y;
                acc[3][c4*4+2] += a3 * w.z; acc[3][c4*4+3] += a3 * w.w;
            }
        }
        __syncthreads();
    }

    // write activations back into A (optionally with relu for the NEXT layer's input)
    #pragma unroll
    for (int r = 0; r < 4; r++) {
        float4* dst = reinterpret_cast<float4*>(A + (ty*4+r) * APAD) + tx * 4;
        #pragma unroll
        for (int c4 = 0; c4 < 4; c4++) {
            float4 v;
            v.x = acc[r][c4*4+0]; v.y = acc[r][c4*4+1];
            v.z = acc[r][c4*4+2]; v.w = acc[r][c4*4+3];
            if (RELU) {
                v.x = fmaxf(v.x, 0.0f); v.y = fmaxf(v.y, 0.0f);
                v.z = fmaxf(v.z, 0.0f); v.w = fmaxf(v.w, 0.0f);
            }
            dst[c4] = v;
        }
    }
    __syncthreads();
}

__global__ void __launch_bounds__(THREADS, 2)
interpnet_kernel(const float* __restrict__ pos_source,
                 const float* __restrict__ pos_target,
                 const float* __restrict__ latents,
                 const int*   __restrict__ row,
                 const int*   __restrict__ col,
                 const float* __restrict__ W_in, const float* __restrict__ b_in,
                 const float* __restrict__ W1,  const float* __restrict__ b1,
                 const float* __restrict__ W2,  const float* __restrict__ b2,
                 const float* __restrict__ W_out, const float* __restrict__ b_out,
                 float* __restrict__ out, int E)
{
    extern __shared__ float smem[];
    float* A  = smem;                 // [64][272]
    float* Wt = A + TM * APAD;        // [16][256]
    int*   sm_col = reinterpret_cast<int*>(Wt + KT * LDIM);  // [64]

    const int tid = threadIdx.x;
    const int e0  = blockIdx.x * TM;

    // ---- gather: pos_rel + zero pad ----
    if (tid < TM) {
        int e  = e0 + tid;
        int ee = (e < E) ? e : (E - 1);
        int r  = row[ee];
        int c  = col[ee];
        sm_col[tid] = c;
        #pragma unroll
        for (int d = 0; d < 3; d++)
            A[tid * APAD + 256 + d] = pos_target[r * 3 + d] - pos_source[c * 3 + d];
        #pragma unroll
        for (int d = 259; d < APAD; d++)
            A[tid * APAD + d] = 0.0f;
    }
    __syncthreads();

    // ---- gather: latents rows (float4, coalesced per 64-thread group) ----
    {
        const float4* lat4 = reinterpret_cast<const float4*>(latents);
        #pragma unroll 4
        for (int idx = tid; idx < TM * 64; idx += THREADS) {
            int m = idx >> 6;
            int v = idx & 63;
            reinterpret_cast<float4*>(A + m * APAD)[v] = lat4[(long)sm_col[m] * 64 + v];
        }
    }
    __syncthreads();

    // ---- 3 dense 256-wide layers, activations in smem ----
    dense256<259, true >(A, Wt, W_in, b_in, tid);  // fc_in,  relu applied for next layer
    dense256<256, true >(A, Wt, W1,   b1,   tid);  // mlp0,   relu applied for next layer
    dense256<256, false>(A, Wt, W2,   b2,   tid);  // mlp1,   raw (fc_out takes it directly)

    // ---- fc_out column 0: out[e] = A[m,:] . W_out[:,0] + b_out[0] ----
    // stage W_out[:,0] into Wt
    Wt[tid] = W_out[tid * 2];   // W_out is [256][2] row-major
    __syncthreads();

    {
        const int m    = tid >> 2;
        const int part = tid & 3;
        const float4* a4 = reinterpret_cast<const float4*>(A + m * APAD) + part * 16;
        const float*  w  = Wt + part * 64;
        float s = 0.0f;
        #pragma unroll
        for (int i = 0; i < 16; i++) {
            float4 av = a4[i];
            s += av.x * w[i*4+0] + av.y * w[i*4+1] + av.z * w[i*4+2] + av.w * w[i*4+3];
        }
        s += __shfl_xor_sync(0xffffffffu, s, 1);
        s += __shfl_xor_sync(0xffffffffu, s, 2);
        if (part == 0) {
            int e = e0 + m;
            if (e < E) out[e] = s + b_out[0];
        }
    }
}

extern "C" void kernel_launch(void* const* d_in, const int* in_sizes, int n_in,
                              void* d_out, int out_size)
{
    const float* pos_source = (const float*)d_in[0];
    const float* pos_target = (const float*)d_in[1];
    const float* latents    = (const float*)d_in[2];
    const int*   row        = (const int*)  d_in[3];
    const int*   col        = (const int*)  d_in[4];
    const float* W_in  = (const float*)d_in[5];
    const float* b_in  = (const float*)d_in[6];
    const float* W1    = (const float*)d_in[7];
    const float* b1    = (const float*)d_in[8];
    const float* W2    = (const float*)d_in[9];
    const float* b2    = (const float*)d_in[10];
    const float* W_out = (const float*)d_in[11];
    const float* b_out = (const float*)d_in[12];
    float* out = (float*)d_out;

    const int E = in_sizes[3];
    const int grid = (E + TM - 1) / TM;

    cudaFuncSetAttribute(interpnet_kernel,
                         cudaFuncAttributeMaxDynamicSharedMemorySize, SMEM_BYTES);
    interpnet_kernel<<<grid, THREADS, SMEM_BYTES>>>(
        pos_source, pos_target, latents, row, col,
        W_in, b_in, W1, b1, W2, b2, W_out, b_out, out, E);
}

// round 2
// speedup vs baseline: 2.9019x; 2.9019x over previous
#include <cuda_runtime.h>
#include <cuda_bf16.h>

// InterpNet fused MLP over gathered edge features — fp32x2 packed-FMA version.
// One CTA per 64-edge tile; activations resident in SMEM across all 4 layers.
// Conflict-free swizzled column ownership + fma.rn.f32x2 dual-issue math.

#define TM      64      // edges per CTA
#define THREADS 256
#define KT      16      // K rows staged per tile
#define LDIM    256
#define APAD    272     // A row stride in floats (>=259, mult of 4, room for K-tile overrun)

#define SMEM_FLOATS (TM*APAD + KT*LDIM + TM)
#define SMEM_BYTES  (SMEM_FLOATS * 4)

typedef unsigned long long ull;

__device__ __forceinline__ ull pack2(float lo, float hi) {
    ull r; asm("mov.b64 %0, {%1, %2};" : "=l"(r) : "f"(lo), "f"(hi)); return r;
}
__device__ __forceinline__ ull bcast2(float v) {
    ull r; asm("mov.b64 %0, {%1, %1};" : "=l"(r) : "f"(v)); return r;
}
__device__ __forceinline__ void fma2(ull& d, ull a, ull b) {
    asm("fma.rn.f32x2 %0, %1, %2, %0;" : "+l"(d) : "l"(a), "l"(b));
}
__device__ __forceinline__ float2 unpack2(ull v) {
    float2 f; asm("mov.b64 {%0, %1}, %2;" : "=f"(f.x), "=f"(f.y) : "l"(v)); return f;
}

// Thread (tx = tid&15, ty = tid>>4) owns rows [ty*4, ty*4+4) and columns
// {c4*64 + tx*4 + i : c4 in 0..3, i in 0..3}  (lane-consecutive float4s -> no LDS conflicts)
template<int K, bool RELU>
__device__ __forceinline__ void dense256(float* __restrict__ A, float* __restrict__ Wt,
                                         const float* __restrict__ W,
                                         const float* __restrict__ b, int tid)
{
    const int tx = tid & 15;
    const int ty = tid >> 4;

    ull acc[4][8];
    {
        const float4* b4 = reinterpret_cast<const float4*>(b);
        #pragma unroll
        for (int c4 = 0; c4 < 4; c4++) {
            float4 bb = b4[c4 * 16 + tx];
            ull p0 = pack2(bb.x, bb.y);
            ull p1 = pack2(bb.z, bb.w);
            #pragma unroll
            for (int r = 0; r < 4; r++) { acc[r][c4*2] = p0; acc[r][c4*2+1] = p1; }
        }
    }

    const int NT = (K + KT - 1) / KT;
    const float4* W4  = reinterpret_cast<const float4*>(W);
    float4*       Wt4 = reinterpret_cast<float4*>(Wt);
    const float4* A4  = reinterpret_cast<const float4*>(A);

    #pragma unroll 1
    for (int t = 0; t < NT; t++) {
        const int k0 = t * KT;
        // stage W[k0:k0+16, :] -> Wt  (float4, coalesced, zero-fill past K)
        #pragma unroll
        for (int j = 0; j < 4; j++) {
            int f    = tid + j * THREADS;
            int krow = k0 + (f >> 6);
            float4 v = make_float4(0.f, 0.f, 0.f, 0.f);
            if (krow < K) v = W4[krow * 64 + (f & 63)];
            Wt4[f] = v;
        }
        __syncthreads();

        const ulonglong2* Wt2 = reinterpret_cast<const ulonglong2*>(Wt);
        #pragma unroll
        for (int kk4 = 0; kk4 < KT / 4; kk4++) {
            float a_[4][4];
            #pragma unroll
            for (int r = 0; r < 4; r++) {
                float4 av = A4[(ty*4 + r) * (APAD/4) + (k0 >> 2) + kk4];
                a_[r][0] = av.x; a_[r][1] = av.y; a_[r][2] = av.z; a_[r][3] = av.w;
            }
            #pragma unroll
            for (int kq = 0; kq < 4; kq++) {
                const int kk = kk4 * 4 + kq;
                ull a2[4];
                #pragma unroll
                for (int r = 0; r < 4; r++) a2[r] = bcast2(a_[r][kq]);
                #pragma unroll
                for (int c4 = 0; c4 < 4; c4++) {
                    ulonglong2 w2 = Wt2[kk * 64 + c4 * 16 + tx];
                    #pragma unroll
                    for (int r = 0; r < 4; r++) {
                        fma2(acc[r][c4*2],   a2[r], w2.x);
                        fma2(acc[r][c4*2+1], a2[r], w2.y);
                    }
                }
            }
        }
        __syncthreads();
    }

    // write activations back (relu applied for the next layer's input)
    #pragma unroll
    for (int r = 0; r < 4; r++) {
        float4* dst = reinterpret_cast<float4*>(A + (ty*4 + r) * APAD);
        #pragma unroll
        for (int c4 = 0; c4 < 4; c4++) {
            float2 lo = unpack2(acc[r][c4*2]);
            float2 hi = unpack2(acc[r][c4*2+1]);
            float4 v  = make_float4(lo.x, lo.y, hi.x, hi.y);
            if (RELU) {
                v.x = fmaxf(v.x, 0.f); v.y = fmaxf(v.y, 0.f);
                v.z = fmaxf(v.z, 0.f); v.w = fmaxf(v.w, 0.f);
            }
            dst[c4 * 16 + tx] = v;
        }
    }
    __syncthreads();
}

__global__ void __launch_bounds__(THREADS, 2)
interpnet_kernel(const float* __restrict__ pos_source,
                 const float* __restrict__ pos_target,
                 const float* __restrict__ latents,
                 const int*   __restrict__ row,
                 const int*   __restrict__ col,
                 const float* __restrict__ W_in, const float* __restrict__ b_in,
                 const float* __restrict__ W1,  const float* __restrict__ b1,
                 const float* __restrict__ W2,  const float* __restrict__ b2,
                 const float* __restrict__ W_out, const float* __restrict__ b_out,
                 float* __restrict__ out, int E)
{
    extern __shared__ float smem[];
    float* A  = smem;                 // [64][272]
    float* Wt = A + TM * APAD;        // [16][256]
    int*   sm_col = reinterpret_cast<int*>(Wt + KT * LDIM);  // [64]

    const int tid = threadIdx.x;
    const int e0  = blockIdx.x * TM;

    // ---- gather: pos_rel + zero pad ----
    if (tid < TM) {
        int e  = e0 + tid;
        int ee = (e < E) ? e : (E - 1);
        int r  = row[ee];
        int c  = col[ee];
        sm_col[tid] = c;
        #pragma unroll
        for (int d = 0; d < 3; d++)
            A[tid * APAD + 256 + d] = pos_target[r * 3 + d] - pos_source[c * 3 + d];
        #pragma unroll
        for (int d = 259; d < APAD; d++)
            A[tid * APAD + d] = 0.0f;
    }
    __syncthreads();

    // ---- gather: latents rows (float4, coalesced per 64-thread group) ----
    {
        const float4* lat4 = reinterpret_cast<const float4*>(latents);
        #pragma unroll 4
        for (int idx = tid; idx < TM * 64; idx += THREADS) {
            int m = idx >> 6;
            int v = idx & 63;
            reinterpret_cast<float4*>(A + m * APAD)[v] = lat4[(long)sm_col[m] * 64 + v];
        }
    }
    __syncthreads();

    // ---- 3 dense 256-wide layers, activations in smem ----
    dense256<259, true >(A, Wt, W_in, b_in, tid);
    dense256<256, true >(A, Wt, W1,   b1,   tid);
    dense256<256, false>(A, Wt, W2,   b2,   tid);

    // ---- fc_out column 0: out[e] = A[m,:] . W_out[:,0] + b_out[0] ----
    Wt[tid] = W_out[tid * 2];   // W_out is [256][2] row-major
    __syncthreads();

    {
        const int m    = tid >> 2;
        const int part = tid & 3;
        const float4* a4 = reinterpret_cast<const float4*>(A + m * APAD) + part * 16;
        const float*  w  = Wt + part * 64;
        float s = 0.0f;
        #pragma unroll
        for (int i = 0; i < 16; i++) {
            float4 av = a4[i];
            s += av.x * w[i*4+0] + av.y * w[i*4+1] + av.z * w[i*4+2] + av.w * w[i*4+3];
        }
        s += __shfl_xor_sync(0xffffffffu, s, 1);
        s += __shfl_xor_sync(0xffffffffu, s, 2);
        if (part == 0) {
            int e = e0 + m;
            if (e < E) out[e] = s + b_out[0];
        }
    }
}

extern "C" void kernel_launch(void* const* d_in, const int* in_sizes, int n_in,
                              void* d_out, int out_size)
{
    const float* pos_source = (const float*)d_in[0];
    const float* pos_target = (const float*)d_in[1];
    const float* latents    = (const float*)d_in[2];
    const int*   row        = (const int*)  d_in[3];
    const int*   col        = (const int*)  d_in[4];
    const float* W_in  = (const float*)d_in[5];
    const float* b_in  = (const float*)d_in[6];
    const float* W1    = (const float*)d_in[7];
    const float* b1    = (const float*)d_in[8];
    const float* W2    = (const float*)d_in[9];
    const float* b2    = (const float*)d_in[10];
    const float* W_out = (const float*)d_in[11];
    const float* b_out = (const float*)d_in[12];
    float* out = (float*)d_out;

    const int E = in_sizes[3];
    const int grid = (E + TM - 1) / TM;

    cudaFuncSetAttribute(interpnet_kernel,
                         cudaFuncAttributeMaxDynamicSharedMemorySize, SMEM_BYTES);
    interpnet_kernel<<<grid, THREADS, SMEM_BYTES>>>(
        pos_source, pos_target, latents, row, col,
        W_in, b_in, W1, b1, W2, b2, W_out, b_out, out, E);
}

// round 5
// speedup vs baseline: 6.5300x; 2.2502x over previous
#include <cuda_runtime.h>
#include <cuda_bf16.h>
#include <cstdint>

// ============================================================================
// InterpNet via mma.sync (HMMA) bf16 2-term split, fp32 accumulate.
// (tcgen05 is unavailable: harness compiles through compute_103 virtual arch,
//  which rejects all 'a'-suffix features. mma.sync/ldmatrix/cp.async are legal.)
//
// CTA: 256 thr = 8 warps (2 M-rows x 4 N-cols), warp tile 64x64.
// CTA tile: M=128 edges, N=256, K=256 per layer, 3 layers fused.
// A (activations, bf16 hi+lo) resident in smem across layers.
// W pre-split+pre-swizzled by prep kernel, cp.async double-buffered 40KB chunks.
// ============================================================================

#define THREADS 256
#define TILE_M  128
#define KC      32
#define CH      40960        // bytes per W chunk (hi 20480 + lo 20480)
#define SW      80           // W smem row stride (64B data + 16B pad)
#define SA      528          // A smem row stride (512B data + 16B pad)
#define NG      24           // 3 layers x 8 chunks

// smem offsets
#define OFF_AH    0
#define OFF_AL    67584
#define OFF_W     135168
#define OFF_BIAS  217088      // f32[3][256]
#define OFF_WP    220160      // f32[3][256]  (W_in rows 256..258)
#define OFF_WOUT  223232      // f32[256]     (W_out[:,0])
#define OFF_POS   224256      // f32[3][128]
#define OFF_RED   225792      // f32[128][4]
#define SMEM_TOTAL 228352

__device__ __align__(16) unsigned char g_wpack[NG * CH];   // 960 KB

// ---------------- helpers ---------------------------------------------------
__device__ __forceinline__ uint32_t smem_u32(const void* p) {
    uint32_t a;
    asm("{ .reg .u64 t; cvta.to.shared.u64 t, %1; cvt.u32.u64 %0, t; }" : "=r"(a) : "l"(p));
    return a;
}
__device__ __forceinline__ uint32_t lds32(uint32_t a) {
    uint32_t v; asm volatile("ld.shared.b32 %0, [%1];" : "=r"(v) : "r"(a)); return v;
}
__device__ __forceinline__ float ldsf(uint32_t a) {
    float v; asm volatile("ld.shared.f32 %0, [%1];" : "=f"(v) : "r"(a)); return v;
}
__device__ __forceinline__ void sts32(uint32_t a, uint32_t v) {
    asm volatile("st.shared.b32 [%0], %1;" :: "r"(a), "r"(v) : "memory");
}
__device__ __forceinline__ void stsf(uint32_t a, float v) {
    asm volatile("st.shared.f32 [%0], %1;" :: "r"(a), "f"(v) : "memory");
}
__device__ __forceinline__ void sts64(uint32_t a, uint32_t v0, uint32_t v1) {
    asm volatile("st.shared.v2.b32 [%0], {%1,%2};" :: "r"(a), "r"(v0), "r"(v1) : "memory");
}
__device__ __forceinline__ void cp16(uint32_t dst, const void* src) {
    asm volatile("cp.async.cg.shared.global [%0], [%1], 16;" :: "r"(dst), "l"(src) : "memory");
}
#define CP_COMMIT() asm volatile("cp.async.commit_group;" ::: "memory")

#define LDSM_X4(r, addr) \
    asm volatile("ldmatrix.sync.aligned.m8n8.x4.shared.b16 {%0,%1,%2,%3}, [%4];" \
        : "=r"((r)[0]), "=r"((r)[1]), "=r"((r)[2]), "=r"((r)[3]) : "r"(addr))

#define MMA16816(d, a, b0, b1) \
    asm volatile("mma.sync.aligned.m16n8k16.row.col.f32.bf16.bf16.f32 " \
        "{%0,%1,%2,%3}, {%4,%5,%6,%7}, {%8,%9}, {%0,%1,%2,%3};" \
        : "+f"((d)[0]), "+f"((d)[1]), "+f"((d)[2]), "+f"((d)[3]) \
        : "r"((a)[0]), "r"((a)[1]), "r"((a)[2]), "r"((a)[3]), "r"(b0), "r"(b1))

// bf16 2-term split of a pair -> packed bf16x2 words (low half = first elem)
__device__ __forceinline__ void split2(float a, float b, uint32_t& hw, uint32_t& lw) {
    __nv_bfloat16 ah = __float2bfloat16_rn(a);
    __nv_bfloat16 bh = __float2bfloat16_rn(b);
    __nv_bfloat16 al = __float2bfloat16_rn(a - __bfloat162float(ah));
    __nv_bfloat16 bl = __float2bfloat16_rn(b - __bfloat162float(bh));
    hw = (uint32_t)__bfloat16_as_ushort(ah) | ((uint32_t)__bfloat16_as_ushort(bh) << 16);
    lw = (uint32_t)__bfloat16_as_ushort(al) | ((uint32_t)__bfloat16_as_ushort(bl) << 16);
}

// ---------------- prep: split weights into the exact smem chunk image -------
// chunk (l,c): rows n=0..255 (stride 80B), k'=0..31 bf16 pairs; hi at +0, lo at +20480
__global__ void prep_weights(const float* __restrict__ W_in,
                             const float* __restrict__ W1,
                             const float* __restrict__ W2)
{
    int t = blockIdx.x * blockDim.x + threadIdx.x;
    if (t >= NG * 256 * 16) return;          // 98304
    int kq = t & 15;
    int n  = (t >> 4) & 255;
    int c  = (t >> 12) & 7;
    int l  = t >> 15;
    const float* W = (l == 0) ? W_in : ((l == 1) ? W1 : W2);
    int k = c * KC + kq * 2;
    uint32_t hw, lw;
    split2(W[k * 256 + n], W[(k + 1) * 256 + n], hw, lw);
    unsigned char* base = g_wpack + (size_t)(l * 8 + c) * CH;
    *(uint32_t*)(base + n * SW + kq * 4)         = hw;
    *(uint32_t*)(base + 20480 + n * SW + kq * 4) = lw;
}

// ---------------- main fused kernel -----------------------------------------
__global__ void __launch_bounds__(THREADS, 1)
interpnet_mma(const float* __restrict__ pos_source,
              const float* __restrict__ pos_target,
              const float* __restrict__ latents,
              const int*   __restrict__ row,
              const int*   __restrict__ col,
              const float* __restrict__ W_in, const float* __restrict__ b_in,
              const float* __restrict__ W1,  const float* __restrict__ b1,
              const float* __restrict__ W2,  const float* __restrict__ b2,
              const float* __restrict__ W_out, const float* __restrict__ b_out,
              float* __restrict__ out, int E)
{
    extern __shared__ unsigned char sm[];
    const uint32_t sb = smem_u32(sm);

    const int tid  = threadIdx.x;
    const int lane = tid & 31;
    const int wid  = tid >> 5;
    const int wr   = wid >> 2;        // 0..1  -> m_base
    const int wc   = wid & 3;         // 0..3  -> n_base
    const int m_base = wr * 64;
    const int n_base = wc * 64;
    const int e0 = blockIdx.x * TILE_M;

    // kick off W chunks 0 and 1 immediately (overlap with gather)
    {
        const unsigned char* src = g_wpack + tid * 16;
        uint32_t dst = sb + OFF_W + tid * 16;
        #pragma unroll
        for (int i = 0; i < 10; i++) cp16(dst + i * 4096, src + i * 4096);
        CP_COMMIT();
        src += CH; dst += CH;
        #pragma unroll
        for (int i = 0; i < 10; i++) cp16(dst + i * 4096, src + i * 4096);
        CP_COMMIT();
    }

    // ---- gather: pos_rel ----
    if (tid < TILE_M) {
        int e  = e0 + tid;
        int ee = (e < E) ? e : (E - 1);
        int r  = row[ee], ci = col[ee];
        #pragma unroll
        for (int d = 0; d < 3; d++)
            stsf(sb + OFF_POS + (d * 128 + tid) * 4,
                 pos_target[r * 3 + d] - pos_source[ci * 3 + d]);
    }
    // ---- gather: latents -> Ah/Al (2 threads per edge) ----
    {
        int m = tid >> 1, half = tid & 1;
        int e  = e0 + m;
        int ee = (e < E) ? e : (E - 1);
        int ci = col[ee];
        const float4* src = (const float4*)latents + (size_t)ci * 64 + half * 32;
        uint32_t dA = sb + OFF_AH + m * SA + half * 256;
        uint32_t dL = sb + OFF_AL + m * SA + half * 256;
        #pragma unroll 4
        for (int j = 0; j < 32; j++) {
            float4 v = src[j];
            uint32_t h0, l0, h1, l1;
            split2(v.x, v.y, h0, l0);
            split2(v.z, v.w, h1, l1);
            sts64(dA + j * 8, h0, h1);
            sts64(dL + j * 8, l0, l1);
        }
    }
    // ---- consts ----
    for (int i = tid; i < 768; i += THREADS) {
        int l = i >> 8, n = i & 255;
        float v = (l == 0) ? b_in[n] : ((l == 1) ? b1[n] : b2[n]);
        stsf(sb + OFF_BIAS + i * 4, v);
    }
    for (int i = tid; i < 768; i += THREADS) {
        int d = i >> 8, n = i & 255;
        stsf(sb + OFF_WP + i * 4, W_in[(256 + d) * 256 + n]);
    }
    if (tid < 256) stsf(sb + OFF_WOUT + tid * 4, W_out[tid * 2]);
    __syncthreads();

    float acc[4][8][4];
    #pragma unroll
    for (int mt = 0; mt < 4; mt++)
        #pragma unroll
        for (int nt = 0; nt < 8; nt++)
            #pragma unroll
            for (int q = 0; q < 4; q++) acc[mt][nt][q] = 0.f;
    float sfin[4][2] = {{0.f,0.f},{0.f,0.f},{0.f,0.f},{0.f,0.f}};

    // ldmatrix A base: lanes 0-15 -> rows, lanes 16-31 -> +16B (k half)
    const uint32_t aH = sb + OFF_AH + (m_base + (lane & 15)) * SA + ((lane >> 4) << 4);
    const uint32_t aL = aH + (OFF_AL - OFF_AH);
    // B base: n = n_base + nt*8 + lane/4 ; packed-k word at (lane&3)*4
    const uint32_t bB = sb + OFF_W + (n_base + (lane >> 2)) * SW + (lane & 3) * 4;

    #pragma unroll 1
    for (int g = 0; g < NG; g++) {
        const int l = g >> 3, c = g & 7, buf = g & 1;
        if (g == NG - 1) asm volatile("cp.async.wait_group 0;" ::: "memory");
        else             asm volatile("cp.async.wait_group 1;" ::: "memory");
        __syncthreads();

        const uint32_t wb = bB + buf * CH;
        #pragma unroll
        for (int ks = 0; ks < 2; ks++) {
            uint32_t ah[4][4], al[4][4];
            const uint32_t ka = (uint32_t)(c * KC + ks * 16) * 2;
            #pragma unroll
            for (int mt = 0; mt < 4; mt++) {
                LDSM_X4(ah[mt], aH + mt * 16 * SA + ka);
                LDSM_X4(al[mt], aL + mt * 16 * SA + ka);
            }
            #pragma unroll
            for (int nt = 0; nt < 8; nt++) {
                uint32_t o = wb + nt * 8 * SW + ks * 32;
                uint32_t bh0 = lds32(o),         bh1 = lds32(o + 16);
                uint32_t bl0 = lds32(o + 20480), bl1 = lds32(o + 20480 + 16);
                #pragma unroll
                for (int mt = 0; mt < 4; mt++) {
                    MMA16816(acc[mt][nt], ah[mt], bh0, bh1);
                    MMA16816(acc[mt][nt], al[mt], bh0, bh1);
                    MMA16816(acc[mt][nt], ah[mt], bl0, bl1);
                }
            }
        }
        __syncthreads();   // all reads of buf + (at layer end) all A reads done

        if (c == 7) {
            // ---- layer epilogue ----
            #pragma unroll
            for (int mt = 0; mt < 4; mt++) {
                const int m_lo = m_base + mt * 16 + (lane >> 2);
                const int m_hi = m_lo + 8;
                float q0l = 0.f, q1l = 0.f, q2l = 0.f, q0h = 0.f, q1h = 0.f, q2h = 0.f;
                if (l == 0) {
                    q0l = ldsf(sb + OFF_POS + (0 * 128 + m_lo) * 4);
                    q1l = ldsf(sb + OFF_POS + (1 * 128 + m_lo) * 4);
                    q2l = ldsf(sb + OFF_POS + (2 * 128 + m_lo) * 4);
                    q0h = ldsf(sb + OFF_POS + (0 * 128 + m_hi) * 4);
                    q1h = ldsf(sb + OFF_POS + (1 * 128 + m_hi) * 4);
                    q2h = ldsf(sb + OFF_POS + (2 * 128 + m_hi) * 4);
                }
                #pragma unroll
                for (int nt = 0; nt < 8; nt++) {
                    const int n0 = n_base + nt * 8 + (lane & 3) * 2;
                    float bi0 = ldsf(sb + OFF_BIAS + (l * 256 + n0) * 4);
                    float bi1 = ldsf(sb + OFF_BIAS + (l * 256 + n0 + 1) * 4);
                    float x00 = acc[mt][nt][0] + bi0, x01 = acc[mt][nt][1] + bi1;
                    float x10 = acc[mt][nt][2] + bi0, x11 = acc[mt][nt][3] + bi1;
                    if (l == 0) {
                        float wa0 = ldsf(sb + OFF_WP + (n0) * 4);
                        float wa1 = ldsf(sb + OFF_WP + (n0 + 1) * 4);
                        float wb0 = ldsf(sb + OFF_WP + (256 + n0) * 4);
                        float wb1 = ldsf(sb + OFF_WP + (256 + n0 + 1) * 4);
                        float wc0 = ldsf(sb + OFF_WP + (512 + n0) * 4);
                        float wc1 = ldsf(sb + OFF_WP + (512 + n0 + 1) * 4);
                        x00 += q0l * wa0 + q1l * wb0 + q2l * wc0;
                        x01 += q0l * wa1 + q1l * wb1 + q2l * wc1;
                        x10 += q0h * wa0 + q1h * wb0 + q2h * wc0;
                        x11 += q0h * wa1 + q1h * wb1 + q2h * wc1;
                    }
                    if (l < 2) {
                        x00 = fmaxf(x00, 0.f); x01 = fmaxf(x01, 0.f);
                        x10 = fmaxf(x10, 0.f); x11 = fmaxf(x11, 0.f);
                        uint32_t hw, lw;
                        split2(x00, x01, hw, lw);
                        sts32(sb + OFF_AH + m_lo * SA + n0 * 2, hw);
                        sts32(sb + OFF_AL + m_lo * SA + n0 * 2, lw);
                        split2(x10, x11, hw, lw);
                        sts32(sb + OFF_AH + m_hi * SA + n0 * 2, hw);
                        sts32(sb + OFF_AL + m_hi * SA + n0 * 2, lw);
                    } else {
                        float wo0 = ldsf(sb + OFF_WOUT + n0 * 4);
                        float wo1 = ldsf(sb + OFF_WOUT + (n0 + 1) * 4);
                        sfin[mt][0] += x00 * wo0 + x01 * wo1;
                        sfin[mt][1] += x10 * wo0 + x11 * wo1;
                    }
                    acc[mt][nt][0] = 0.f; acc[mt][nt][1] = 0.f;
                    acc[mt][nt][2] = 0.f; acc[mt][nt][3] = 0.f;
                }
            }
            // A writes become visible at the next top-of-loop __syncthreads
        }

        if (g + 2 < NG) {
            const unsigned char* src = g_wpack + (size_t)(g + 2) * CH + tid * 16;
            uint32_t dst = sb + OFF_W + buf * CH + tid * 16;
            #pragma unroll
            for (int i = 0; i < 10; i++) cp16(dst + i * 4096, src + i * 4096);
            CP_COMMIT();
        }
    }

    // ---- final reduce: sum over n within lane-quads, then across warp-cols ----
    #pragma unroll
    for (int mt = 0; mt < 4; mt++) {
        float s0 = sfin[mt][0], s1 = sfin[mt][1];
        s0 += __shfl_xor_sync(0xffffffffu, s0, 1);
        s0 += __shfl_xor_sync(0xffffffffu, s0, 2);
        s1 += __shfl_xor_sync(0xffffffffu, s1, 1);
        s1 += __shfl_xor_sync(0xffffffffu, s1, 2);
        if ((lane & 3) == 0) {
            int m_lo = m_base + mt * 16 + (lane >> 2);
            stsf(sb + OFF_RED + (m_lo * 4 + wc) * 4, s0);
            stsf(sb + OFF_RED + ((m_lo + 8) * 4 + wc) * 4, s1);
        }
    }
    __syncthreads();
    if (tid < TILE_M) {
        float s = ldsf(sb + OFF_RED + (tid * 4 + 0) * 4)
                + ldsf(sb + OFF_RED + (tid * 4 + 1) * 4)
                + ldsf(sb + OFF_RED + (tid * 4 + 2) * 4)
                + ldsf(sb + OFF_RED + (tid * 4 + 3) * 4);
        int e = e0 + tid;
        if (e < E) out[e] = s + __ldg(b_out);
    }
}

// ---------------- launch -----------------------------------------------------
extern "C" void kernel_launch(void* const* d_in, const int* in_sizes, int n_in,
                              void* d_out, int out_size)
{
    const float* pos_source = (const float*)d_in[0];
    const float* pos_target = (const float*)d_in[1];
    const float* latents    = (const float*)d_in[2];
    const int*   row        = (const int*)  d_in[3];
    const int*   col        = (const int*)  d_in[4];
    const float* W_in  = (const float*)d_in[5];
    const float* b_in  = (const float*)d_in[6];
    const float* W1    = (const float*)d_in[7];
    const float* b1    = (const float*)d_in[8];
    const float* W2    = (const float*)d_in[9];
    const float* b2    = (const float*)d_in[10];
    const float* W_out = (const float*)d_in[11];
    const float* b_out = (const float*)d_in[12];
    float* out = (float*)d_out;

    const int E = in_sizes[3];

    prep_weights<<<(NG * 256 * 16 + 255) / 256, 256>>>(W_in, W1, W2);

    cudaFuncSetAttribute(interpnet_mma,
                         cudaFuncAttributeMaxDynamicSharedMemorySize, SMEM_TOTAL);
    const int grid = (E + TILE_M - 1) / TILE_M;
    interpnet_mma<<<grid, THREADS, SMEM_TOTAL>>>(
        pos_source, pos_target, latents, row, col,
        W_in, b_in, W1, b1, W2, b2, W_out, b_out, out, E);
}

// round 7
// speedup vs baseline: 7.2075x; 1.1038x over previous
#include <cuda_runtime.h>
#include <cuda_bf16.h>
#include <cstdint>

// ============================================================================
// InterpNet via mma.sync (HMMA) bf16 2-term split, fp32 accumulate.
// Round 6: persistent CTAs, pre-split latents (cp.async gather), hoisted
// ldmatrix frags, epilogue loop-order swap, one-time consts.
// ============================================================================

#define THREADS 256
#define TILE_M  128
#define KC      32
#define CH      40960        // bytes per W chunk (hi 20480 + lo 20480)
#define SW      80           // W smem row stride
#define SA      528          // A smem row stride
#define NG      24           // 3 layers x 8 chunks
#define NSRC_MAX 100000

// smem offsets
#define OFF_AH    0
#define OFF_AL    67584
#define OFF_W     135168
#define OFF_BIAS  217088      // f32[3][256]
#define OFF_WP    220160      // f32[3][256]
#define OFF_WOUT  223232      // f32[256]
#define OFF_POS   224256      // f32[3][128]
#define OFF_RED   225792      // f32[128][4]
#define SMEM_TOTAL 228352

__device__ __align__(16) unsigned char g_wpack[NG * CH];                 // 960 KB
__device__ __align__(16) unsigned char g_latpack[(size_t)NSRC_MAX * 1024]; // 102 MB

// ---------------- helpers ---------------------------------------------------
__device__ __forceinline__ uint32_t smem_u32(const void* p) {
    uint32_t a;
    asm("{ .reg .u64 t; cvta.to.shared.u64 t, %1; cvt.u32.u64 %0, t; }" : "=r"(a) : "l"(p));
    return a;
}
__device__ __forceinline__ uint32_t lds32(uint32_t a) {
    uint32_t v; asm volatile("ld.shared.b32 %0, [%1];" : "=r"(v) : "r"(a)); return v;
}
__device__ __forceinline__ float ldsf(uint32_t a) {
    float v; asm volatile("ld.shared.f32 %0, [%1];" : "=f"(v) : "r"(a)); return v;
}
__device__ __forceinline__ void sts32(uint32_t a, uint32_t v) {
    asm volatile("st.shared.b32 [%0], %1;" :: "r"(a), "r"(v) : "memory");
}
__device__ __forceinline__ void stsf(uint32_t a, float v) {
    asm volatile("st.shared.f32 [%0], %1;" :: "r"(a), "f"(v) : "memory");
}
__device__ __forceinline__ void cp16(uint32_t dst, const void* src) {
    asm volatile("cp.async.cg.shared.global [%0], [%1], 16;" :: "r"(dst), "l"(src) : "memory");
}
#define CP_COMMIT() asm volatile("cp.async.commit_group;" ::: "memory")

#define LDSM_X4(r, addr) \
    asm volatile("ldmatrix.sync.aligned.m8n8.x4.shared.b16 {%0,%1,%2,%3}, [%4];" \
        : "=r"((r)[0]), "=r"((r)[1]), "=r"((r)[2]), "=r"((r)[3]) : "r"(addr))

#define MMA16816(d, a, b0, b1) \
    asm volatile("mma.sync.aligned.m16n8k16.row.col.f32.bf16.bf16.f32 " \
        "{%0,%1,%2,%3}, {%4,%5,%6,%7}, {%8,%9}, {%0,%1,%2,%3};" \
        : "+f"((d)[0]), "+f"((d)[1]), "+f"((d)[2]), "+f"((d)[3]) \
        : "r"((a)[0]), "r"((a)[1]), "r"((a)[2]), "r"((a)[3]), "r"(b0), "r"(b1))

__device__ __forceinline__ void split2(float a, float b, uint32_t& hw, uint32_t& lw) {
    __nv_bfloat16 ah = __float2bfloat16_rn(a);
    __nv_bfloat16 bh = __float2bfloat16_rn(b);
    __nv_bfloat16 al = __float2bfloat16_rn(a - __bfloat162float(ah));
    __nv_bfloat16 bl = __float2bfloat16_rn(b - __bfloat162float(bh));
    hw = (uint32_t)__bfloat16_as_ushort(ah) | ((uint32_t)__bfloat16_as_ushort(bh) << 16);
    lw = (uint32_t)__bfloat16_as_ushort(al) | ((uint32_t)__bfloat16_as_ushort(bl) << 16);
}

// ---------------- prep kernels ----------------------------------------------
__global__ void prep_weights(const float* __restrict__ W_in,
                             const float* __restrict__ W1,
                             const float* __restrict__ W2)
{
    int t = blockIdx.x * blockDim.x + threadIdx.x;
    if (t >= NG * 256 * 16) return;
    int kq = t & 15;
    int n  = (t >> 4) & 255;
    int c  = (t >> 12) & 7;
    int l  = t >> 15;
    const float* W = (l == 0) ? W_in : ((l == 1) ? W1 : W2);
    int k = c * KC + kq * 2;
    uint32_t hw, lw;
    split2(W[k * 256 + n], W[(k + 1) * 256 + n], hw, lw);
    unsigned char* base = g_wpack + (size_t)(l * 8 + c) * CH;
    *(uint32_t*)(base + n * SW + kq * 4)         = hw;
    *(uint32_t*)(base + 20480 + n * SW + kq * 4) = lw;
}

// split latents rows into [hi 512B | lo 512B] per row
__global__ void prep_latents(const float* __restrict__ lat, int nrows)
{
    long t = (long)blockIdx.x * blockDim.x + threadIdx.x;
    if (t >= (long)nrows * 64) return;
    long r = t >> 6;
    int  q = (int)(t & 63);
    float4 v = ((const float4*)lat)[t];
    uint32_t h0, l0, h1, l1;
    split2(v.x, v.y, h0, l0);
    split2(v.z, v.w, h1, l1);
    *(uint2*)(g_latpack + r * 1024 + q * 8)       = make_uint2(h0, h1);
    *(uint2*)(g_latpack + r * 1024 + 512 + q * 8) = make_uint2(l0, l1);
}

// ---------------- device subroutines ----------------------------------------
__device__ __forceinline__ void gather_tile(uint32_t sb, int tid, int t, int E,
                                            const int* __restrict__ col)
{
    int gm = tid >> 1, gh = tid & 1;
    int e  = t * TILE_M + gm;
    int ee = (e < E) ? e : (E - 1);
    int ci = col[ee];
    const unsigned char* srow = g_latpack + (size_t)ci * 1024 + gh * 256;
    uint32_t dA = sb + OFF_AH + gm * SA + gh * 256;
    uint32_t dL = sb + OFF_AL + gm * SA + gh * 256;
    #pragma unroll
    for (int j = 0; j < 16; j++) cp16(dA + j * 16, srow + j * 16);
    #pragma unroll
    for (int j = 0; j < 16; j++) cp16(dL + j * 16, srow + 512 + j * 16);
    CP_COMMIT();
}

__device__ __forceinline__ void pos_tile(uint32_t sb, int tid, int t, int E,
                                         const int* __restrict__ row,
                                         const int* __restrict__ col,
                                         const float* __restrict__ pt,
                                         const float* __restrict__ ps)
{
    if (tid < TILE_M) {
        int e  = t * TILE_M + tid;
        int ee = (e < E) ? e : (E - 1);
        int r  = row[ee], ci = col[ee];
        #pragma unroll
        for (int d = 0; d < 3; d++)
            stsf(sb + OFF_POS + (d * 128 + tid) * 4, pt[r * 3 + d] - ps[ci * 3 + d]);
    }
}

__device__ __forceinline__ void epilogue01(uint32_t sb, int l, int lane,
                                           int m_base, int n_base,
                                           float acc[4][8][4])
{
    float qv[3][4][2];
    if (l == 0) {
        #pragma unroll
        for (int mt = 0; mt < 4; mt++) {
            int m_lo = m_base + mt * 16 + (lane >> 2);
            #pragma unroll
            for (int d = 0; d < 3; d++) {
                qv[d][mt][0] = ldsf(sb + OFF_POS + (d * 128 + m_lo) * 4);
                qv[d][mt][1] = ldsf(sb + OFF_POS + (d * 128 + m_lo + 8) * 4);
            }
        }
    }
    #pragma unroll
    for (int nt = 0; nt < 8; nt++) {
        const int n0 = n_base + nt * 8 + (lane & 3) * 2;
        float bi0 = ldsf(sb + OFF_BIAS + (l * 256 + n0) * 4);
        float bi1 = ldsf(sb + OFF_BIAS + (l * 256 + n0 + 1) * 4);
        float wa0 = 0.f, wa1 = 0.f, wb0 = 0.f, wb1 = 0.f, wc0 = 0.f, wc1 = 0.f;
        if (l == 0) {
            wa0 = ldsf(sb + OFF_WP + n0 * 4);           wa1 = ldsf(sb + OFF_WP + (n0 + 1) * 4);
            wb0 = ldsf(sb + OFF_WP + (256 + n0) * 4);   wb1 = ldsf(sb + OFF_WP + (256 + n0 + 1) * 4);
            wc0 = ldsf(sb + OFF_WP + (512 + n0) * 4);   wc1 = ldsf(sb + OFF_WP + (512 + n0 + 1) * 4);
        }
        #pragma unroll
        for (int mt = 0; mt < 4; mt++) {
            const int m_lo = m_base + mt * 16 + (lane >> 2);
            float x00 = acc[mt][nt][0] + bi0, x01 = acc[mt][nt][1] + bi1;
            float x10 = acc[mt][nt][2] + bi0, x11 = acc[mt][nt][3] + bi1;
            if (l == 0) {
                x00 += qv[0][mt][0] * wa0 + qv[1][mt][0] * wb0 + qv[2][mt][0] * wc0;
                x01 += qv[0][mt][0] * wa1 + qv[1][mt][0] * wb1 + qv[2][mt][0] * wc1;
                x10 += qv[0][mt][1] * wa0 + qv[1][mt][1] * wb0 + qv[2][mt][1] * wc0;
                x11 += qv[0][mt][1] * wa1 + qv[1][mt][1] * wb1 + qv[2][mt][1] * wc1;
            }
            x00 = fmaxf(x00, 0.f); x01 = fmaxf(x01, 0.f);
            x10 = fmaxf(x10, 0.f); x11 = fmaxf(x11, 0.f);
            uint32_t hw, lw;
            split2(x00, x01, hw, lw);
            sts32(sb + OFF_AH + m_lo * SA + n0 * 2, hw);
            sts32(sb + OFF_AL + m_lo * SA + n0 * 2, lw);
            split2(x10, x11, hw, lw);
            sts32(sb + OFF_AH + (m_lo + 8) * SA + n0 * 2, hw);
            sts32(sb + OFF_AL + (m_lo + 8) * SA + n0 * 2, lw);
            acc[mt][nt][0] = 0.f; acc[mt][nt][1] = 0.f;
            acc[mt][nt][2] = 0.f; acc[mt][nt][3] = 0.f;
        }
    }
}

// ---------------- main persistent kernel ------------------------------------
__global__ void __launch_bounds__(THREADS, 1)
interpnet_mma(const float* __restrict__ pos_source,
              const float* __restrict__ pos_target,
              const int*   __restrict__ row,
              const int*   __restrict__ col,
              const float* __restrict__ W_in, const float* __restrict__ b_in,
              const float* __restrict__ b1,  const float* __restrict__ b2,
              const float* __restrict__ W_out, const float* __restrict__ b_out,
              float* __restrict__ out, int E, int ntiles)
{
    extern __shared__ unsigned char sm[];
    const uint32_t sb = smem_u32(sm);

    const int tid  = threadIdx.x;
    const int lane = tid & 31;
    const int wid  = tid >> 5;
    const int m_base = (wid >> 2) * 64;
    const int n_base = (wid & 3) * 64;

    // ---- one-time consts ----
    for (int i = tid; i < 768; i += THREADS) {
        int l = i >> 8, n = i & 255;
        float v = (l == 0) ? b_in[n] : ((l == 1) ? b1[n] : b2[n]);
        stsf(sb + OFF_BIAS + i * 4, v);
    }
    for (int i = tid; i < 768; i += THREADS) {
        int d = i >> 8, n = i & 255;
        stsf(sb + OFF_WP + i * 4, W_in[(256 + d) * 256 + n]);
    }
    if (tid < 256) stsf(sb + OFF_WOUT + tid * 4, W_out[tid * 2]);

    const int t0 = blockIdx.x;
    if (t0 < ntiles) {
        // W chunks 0,1
        const unsigned char* src = g_wpack + tid * 16;
        uint32_t dst = sb + OFF_W + tid * 16;
        #pragma unroll
        for (int i = 0; i < 10; i++) cp16(dst + i * 4096, src + i * 4096);
        CP_COMMIT();
        src += CH; dst += CH;
        #pragma unroll
        for (int i = 0; i < 10; i++) cp16(dst + i * 4096, src + i * 4096);
        CP_COMMIT();
        // A gather + pos for first tile
        gather_tile(sb, tid, t0, E, col);
        pos_tile(sb, tid, t0, E, row, col, pos_target, pos_source);
    }

    const uint32_t aH = sb + OFF_AH + (m_base + (lane & 15)) * SA + ((lane >> 4) << 4);
    const uint32_t aL = aH + (OFF_AL - OFF_AH);
    const uint32_t bB = sb + OFF_W + (n_base + (lane >> 2)) * SW + (lane & 3) * 4;

    #pragma unroll 1
    for (int t = t0; t < ntiles; t += gridDim.x) {
        const bool last = (t + (int)gridDim.x >= ntiles);

        float acc[4][8][4];
        #pragma unroll
        for (int mt = 0; mt < 4; mt++)
            #pragma unroll
            for (int nt = 0; nt < 8; nt++)
                #pragma unroll
                for (int q = 0; q < 4; q++) acc[mt][nt][q] = 0.f;

        #pragma unroll 1
        for (int g = 0; g < NG; g++) {
            const int l = g >> 3, c = g & 7, buf = g & 1;
            const uint32_t ka0 = (uint32_t)(c * KC) * 2;

            uint32_t ah0[4][4], al0[4][4];
            if (c) {   // within layer: A is stable, hoist frags above the wait
                #pragma unroll
                for (int mt = 0; mt < 4; mt++) {
                    LDSM_X4(ah0[mt], aH + mt * 16 * SA + ka0);
                    LDSM_X4(al0[mt], aL + mt * 16 * SA + ka0);
                }
            }
            if (g == 0) asm volatile("cp.async.wait_group 0;" ::: "memory");
            else        asm volatile("cp.async.wait_group 1;" ::: "memory");
            __syncthreads();
            if (!c) {
                #pragma unroll
                for (int mt = 0; mt < 4; mt++) {
                    LDSM_X4(ah0[mt], aH + mt * 16 * SA + ka0);
                    LDSM_X4(al0[mt], aL + mt * 16 * SA + ka0);
                }
            }

            const uint32_t wb = bB + buf * CH;
            // ks = 0
            #pragma unroll
            for (int nt = 0; nt < 8; nt++) {
                uint32_t o = wb + nt * 8 * SW;
                uint32_t bh0 = lds32(o),         bh1 = lds32(o + 16);
                uint32_t bl0 = lds32(o + 20480), bl1 = lds32(o + 20480 + 16);
                #pragma unroll
                for (int mt = 0; mt < 4; mt++) {
                    MMA16816(acc[mt][nt], ah0[mt], bh0, bh1);
                    MMA16816(acc[mt][nt], al0[mt], bh0, bh1);
                    MMA16816(acc[mt][nt], ah0[mt], bl0, bl1);
                }
            }
            // ks = 1
            {
                uint32_t ah1[4][4], al1[4][4];
                const uint32_t ka1 = ka0 + 32;
                #pragma unroll
                for (int mt = 0; mt < 4; mt++) {
                    LDSM_X4(ah1[mt], aH + mt * 16 * SA + ka1);
                    LDSM_X4(al1[mt], aL + mt * 16 * SA + ka1);
                }
                #pragma unroll
                for (int nt = 0; nt < 8; nt++) {
                    uint32_t o = wb + nt * 8 * SW + 32;
                    uint32_t bh0 = lds32(o),         bh1 = lds32(o + 16);
                    uint32_t bl0 = lds32(o + 20480), bl1 = lds32(o + 20480 + 16);
                    #pragma unroll
                    for (int mt = 0; mt < 4; mt++) {
                        MMA16816(acc[mt][nt], ah1[mt], bh0, bh1);
                        MMA16816(acc[mt][nt], al1[mt], bh0, bh1);
                        MMA16816(acc[mt][nt], ah1[mt], bl0, bl1);
                    }
                }
            }
            __syncthreads();

            // stream next chunk (wraps into next tile's chunks 0,1)
            int cn = g + 2;
            bool issue = true;
            if (cn >= NG) { cn -= NG; issue = !last; }
            if (issue) {
                const unsigned char* csrc = g_wpack + (size_t)cn * CH + tid * 16;
                uint32_t cdst = sb + OFF_W + buf * CH + tid * 16;
                #pragma unroll
                for (int i = 0; i < 10; i++) cp16(cdst + i * 4096, csrc + i * 4096);
                CP_COMMIT();
            }

            if (c == 7 && l < 2) epilogue01(sb, l, lane, m_base, n_base, acc);
        }

        // ---- tile boundary: overlap next-tile gather with final epilogue ----
        const int t2 = t + (int)gridDim.x;
        if (t2 < ntiles) {
            gather_tile(sb, tid, t2, E, col);
            pos_tile(sb, tid, t2, E, row, col, pos_target, pos_source);
        }

        // layer-2 epilogue: project to W_out[:,0]
        float sfin[4][2] = {{0.f,0.f},{0.f,0.f},{0.f,0.f},{0.f,0.f}};
        #pragma unroll
        for (int nt = 0; nt < 8; nt++) {
            const int n0 = n_base + nt * 8 + (lane & 3) * 2;
            float wo0 = ldsf(sb + OFF_WOUT + n0 * 4);
            float wo1 = ldsf(sb + OFF_WOUT + (n0 + 1) * 4);
            float bi0 = ldsf(sb + OFF_BIAS + (512 + n0) * 4);
            float bi1 = ldsf(sb + OFF_BIAS + (512 + n0 + 1) * 4);
            #pragma unroll
            for (int mt = 0; mt < 4; mt++) {
                sfin[mt][0] += (acc[mt][nt][0] + bi0) * wo0 + (acc[mt][nt][1] + bi1) * wo1;
                sfin[mt][1] += (acc[mt][nt][2] + bi0) * wo0 + (acc[mt][nt][3] + bi1) * wo1;
            }
        }
        #pragma unroll
        for (int mt = 0; mt < 4; mt++) {
            float s0 = sfin[mt][0], s1 = sfin[mt][1];
            s0 += __shfl_xor_sync(0xffffffffu, s0, 1);
            s0 += __shfl_xor_sync(0xffffffffu, s0, 2);
            s1 += __shfl_xor_sync(0xffffffffu, s1, 1);
            s1 += __shfl_xor_sync(0xffffffffu, s1, 2);
            if ((lane & 3) == 0) {
                int m_lo = m_base + mt * 16 + (lane >> 2);
                stsf(sb + OFF_RED + (m_lo * 4 + (wid & 3)) * 4, s0);
                stsf(sb + OFF_RED + ((m_lo + 8) * 4 + (wid & 3)) * 4, s1);
            }
        }
        __syncthreads();
        if (tid < TILE_M) {
            float s = ldsf(sb + OFF_RED + (tid * 4 + 0) * 4)
                    + ldsf(sb + OFF_RED + (tid * 4 + 1) * 4)
                    + ldsf(sb + OFF_RED + (tid * 4 + 2) * 4)
                    + ldsf(sb + OFF_RED + (tid * 4 + 3) * 4);
            int e = t * TILE_M + tid;
            if (e < E) out[e] = s + __ldg(b_out);
        }
    }
}

// ---------------- launch -----------------------------------------------------
extern "C" void kernel_launch(void* const* d_in, const int* in_sizes, int n_in,
                              void* d_out, int out_size)
{
    const float* pos_source = (const float*)d_in[0];
    const float* pos_target = (const float*)d_in[1];
    const float* latents    = (const float*)d_in[2];
    const int*   row        = (const int*)  d_in[3];
    const int*   col        = (const int*)  d_in[4];
    const float* W_in  = (const float*)d_in[5];
    const float* b_in  = (const float*)d_in[6];
    const float* W1    = (const float*)d_in[7];
    const float* b1    = (const float*)d_in[8];
    const float* W2    = (const float*)d_in[9];
    const float* b2    = (const float*)d_in[10];
    const float* W_out = (const float*)d_in[11];
    const float* b_out = (const float*)d_in[12];
    float* out = (float*)d_out;

    const int E = in_sizes[3];
    int nrows = in_sizes[2] / 256;
    if (nrows > NSRC_MAX) nrows = NSRC_MAX;

    prep_weights<<<(NG * 256 * 16 + 255) / 256, 256>>>(W_in, W1, W2);
    prep_latents<<<(int)(((long)nrows * 64 + 255) / 256), 256>>>(latents, nrows);

    int numSMs = 148;
    cudaDeviceGetAttribute(&numSMs, cudaDevAttrMultiProcessorCount, 0);

    const int ntiles = (E + TILE_M - 1) / TILE_M;
    int grid = numSMs < ntiles ? numSMs : ntiles;

    cudaFuncSetAttribute(interpnet_mma,
                         cudaFuncAttributeMaxDynamicSharedMemorySize, SMEM_TOTAL);
    interpnet_mma<<<grid, THREADS, SMEM_TOTAL>>>(
        pos_source, pos_target, row, col,
        W_in, b_in, b1, b2, W_out, b_out, out, E, ntiles);
}

// round 9
// speedup vs baseline: 10.9377x; 1.5175x over previous
#include <cuda_runtime.h>
#include <cuda_fp16.h>
#include <cstdint>

// ============================================================================
// InterpNet via mma.sync HMMA, fp16 asymmetric split:
//   A (activations): single fp16        (error ~2^-12 relative, dominates)
//   B (weights):     2-plane fp16 split (Bh + Bl, pre-scaled x16 -> exact)
// => 2 MMA terms per k-step (was 3 bf16 terms), fp32 accumulate.
// Persistent CTAs, cp.async W streaming + latent gather, A resident in smem.
// ============================================================================

#define THREADS 256
#define TILE_M  128
#define KC      32
#define CH      40960        // bytes per W chunk (hi 20480 + lo 20480)
#define SW      80           // W smem row stride
#define SA      528          // A smem row stride (512B fp16 + 16B pad)
#define NG      24           // 3 layers x 8 chunks
#define NSRC_MAX 100000
#define WSCALE   16.0f
#define WINV     0.0625f

// smem offsets
#define OFF_AH    0           // fp16 A [128][264] (528B rows)      67584
#define OFF_W     67584       // W double buffer 2 x 40960          81920
#define OFF_BIAS  149504      // f32[3][256]
#define OFF_WP    152576      // f32[3][256]
#define OFF_WOUT  155648      // f32[256]
#define OFF_POS   156672      // f32[3][128]
#define OFF_RED   158208      // f32[128][4]
#define SMEM_TOTAL 160256

__device__ __align__(16) unsigned char g_wpack[NG * CH];                  // 960 KB
__device__ __align__(16) unsigned char g_latpack[(size_t)NSRC_MAX * 512]; // 51.2 MB

// ---------------- helpers ---------------------------------------------------
__device__ __forceinline__ uint32_t smem_u32(const void* p) {
    uint32_t a;
    asm("{ .reg .u64 t; cvta.to.shared.u64 t, %1; cvt.u32.u64 %0, t; }" : "=r"(a) : "l"(p));
    return a;
}
__device__ __forceinline__ uint32_t lds32(uint32_t a) {
    uint32_t v; asm volatile("ld.shared.b32 %0, [%1];" : "=r"(v) : "r"(a)); return v;
}
__device__ __forceinline__ float ldsf(uint32_t a) {
    float v; asm volatile("ld.shared.f32 %0, [%1];" : "=f"(v) : "r"(a)); return v;
}
__device__ __forceinline__ void sts32(uint32_t a, uint32_t v) {
    asm volatile("st.shared.b32 [%0], %1;" :: "r"(a), "r"(v) : "memory");
}
__device__ __forceinline__ void stsf(uint32_t a, float v) {
    asm volatile("st.shared.f32 [%0], %1;" :: "r"(a), "f"(v) : "memory");
}
__device__ __forceinline__ void cp16(uint32_t dst, const void* src) {
    asm volatile("cp.async.cg.shared.global [%0], [%1], 16;" :: "r"(dst), "l"(src) : "memory");
}
#define CP_COMMIT() asm volatile("cp.async.commit_group;" ::: "memory")

#define LDSM_X4(r, addr) \
    asm volatile("ldmatrix.sync.aligned.m8n8.x4.shared.b16 {%0,%1,%2,%3}, [%4];" \
        : "=r"((r)[0]), "=r"((r)[1]), "=r"((r)[2]), "=r"((r)[3]) : "r"(addr))

#define MMAF16(d, a, b0, b1) \
    asm volatile("mma.sync.aligned.m16n8k16.row.col.f32.f16.f16.f32 " \
        "{%0,%1,%2,%3}, {%4,%5,%6,%7}, {%8,%9}, {%0,%1,%2,%3};" \
        : "+f"((d)[0]), "+f"((d)[1]), "+f"((d)[2]), "+f"((d)[3]) \
        : "r"((a)[0]), "r"((a)[1]), "r"((a)[2]), "r"((a)[3]), "r"(b0), "r"(b1))

// pack two f32 -> f16x2 word (lo half = first arg)
__device__ __forceinline__ uint32_t packh2(float lo, float hi) {
    uint32_t r; asm("cvt.rn.f16x2.f32 %0, %1, %2;" : "=r"(r) : "f"(hi), "f"(lo)); return r;
}
// 2-term fp16 split of a pair (scaled values) -> hi-plane word, lo-plane word
__device__ __forceinline__ void splith(float a, float b, uint32_t& hw, uint32_t& lw) {
    __half ah = __float2half_rn(a);
    __half bh = __float2half_rn(b);
    __half al = __float2half_rn(a - __half2float(ah));
    __half bl = __float2half_rn(b - __half2float(bh));
    hw = (uint32_t)__half_as_ushort(ah) | ((uint32_t)__half_as_ushort(bh) << 16);
    lw = (uint32_t)__half_as_ushort(al) | ((uint32_t)__half_as_ushort(bl) << 16);
}

// ---------------- prep kernels ----------------------------------------------
__global__ void prep_weights(const float* __restrict__ W_in,
                             const float* __restrict__ W1,
                             const float* __restrict__ W2)
{
    int t = blockIdx.x * blockDim.x + threadIdx.x;
    if (t >= NG * 256 * 16) return;
    int kq = t & 15;
    int n  = (t >> 4) & 255;
    int c  = (t >> 12) & 7;
    int l  = t >> 15;
    const float* W = (l == 0) ? W_in : ((l == 1) ? W1 : W2);
    int k = c * KC + kq * 2;
    uint32_t hw, lw;
    splith(W[k * 256 + n] * WSCALE, W[(k + 1) * 256 + n] * WSCALE, hw, lw);
    unsigned char* base = g_wpack + (size_t)(l * 8 + c) * CH;
    *(uint32_t*)(base + n * SW + kq * 4)         = hw;
    *(uint32_t*)(base + 20480 + n * SW + kq * 4) = lw;
}

// latents -> single fp16 plane, 512B per row
__global__ void prep_latents(const float* __restrict__ lat, int nrows)
{
    long t = (long)blockIdx.x * blockDim.x + threadIdx.x;
    if (t >= (long)nrows * 64) return;
    long r = t >> 6;
    int  q = (int)(t & 63);
    float4 v = ((const float4*)lat)[t];
    *(uint2*)(g_latpack + r * 512 + q * 8) =
        make_uint2(packh2(v.x, v.y), packh2(v.z, v.w));
}

// ---------------- device subroutines ----------------------------------------
__device__ __forceinline__ void gather_tile(uint32_t sb, int tid, int t, int E,
                                            const int* __restrict__ col)
{
    int gm = tid >> 1, gh = tid & 1;     // 2 threads per edge, 256B each
    int e  = t * TILE_M + gm;
    int ee = (e < E) ? e : (E - 1);
    int ci = col[ee];
    const unsigned char* srow = g_latpack + (size_t)ci * 512 + gh * 256;
    uint32_t dA = sb + OFF_AH + gm * SA + gh * 256;
    #pragma unroll
    for (int j = 0; j < 16; j++) cp16(dA + j * 16, srow + j * 16);
    CP_COMMIT();
}

__device__ __forceinline__ void pos_tile(uint32_t sb, int tid, int t, int E,
                                         const int* __restrict__ row,
                                         const int* __restrict__ col,
                                         const float* __restrict__ pt,
                                         const float* __restrict__ ps)
{
    if (tid < TILE_M) {
        int e  = t * TILE_M + tid;
        int ee = (e < E) ? e : (E - 1);
        int r  = row[ee], ci = col[ee];
        #pragma unroll
        for (int d = 0; d < 3; d++)
            stsf(sb + OFF_POS + (d * 128 + tid) * 4, pt[r * 3 + d] - ps[ci * 3 + d]);
    }
}

__device__ __forceinline__ void epilogue01(uint32_t sb, int l, int lane,
                                           int m_base, int n_base,
                                           float acc[4][8][4])
{
    float qv[3][4][2];
    if (l == 0) {
        #pragma unroll
        for (int mt = 0; mt < 4; mt++) {
            int m_lo = m_base + mt * 16 + (lane >> 2);
            #pragma unroll
            for (int d = 0; d < 3; d++) {
                qv[d][mt][0] = ldsf(sb + OFF_POS + (d * 128 + m_lo) * 4);
                qv[d][mt][1] = ldsf(sb + OFF_POS + (d * 128 + m_lo + 8) * 4);
            }
        }
    }
    #pragma unroll
    for (int nt = 0; nt < 8; nt++) {
        const int n0 = n_base + nt * 8 + (lane & 3) * 2;
        float bi0 = ldsf(sb + OFF_BIAS + (l * 256 + n0) * 4);
        float bi1 = ldsf(sb + OFF_BIAS + (l * 256 + n0 + 1) * 4);
        float wa0 = 0.f, wa1 = 0.f, wb0 = 0.f, wb1 = 0.f, wc0 = 0.f, wc1 = 0.f;
        if (l == 0) {
            wa0 = ldsf(sb + OFF_WP + n0 * 4);           wa1 = ldsf(sb + OFF_WP + (n0 + 1) * 4);
            wb0 = ldsf(sb + OFF_WP + (256 + n0) * 4);   wb1 = ldsf(sb + OFF_WP + (256 + n0 + 1) * 4);
            wc0 = ldsf(sb + OFF_WP + (512 + n0) * 4);   wc1 = ldsf(sb + OFF_WP + (512 + n0 + 1) * 4);
        }
        #pragma unroll
        for (int mt = 0; mt < 4; mt++) {
            const int m_lo = m_base + mt * 16 + (lane >> 2);
            float x00 = acc[mt][nt][0] * WINV + bi0, x01 = acc[mt][nt][1] * WINV + bi1;
            float x10 = acc[mt][nt][2] * WINV + bi0, x11 = acc[mt][nt][3] * WINV + bi1;
            if (l == 0) {
                x00 += qv[0][mt][0] * wa0 + qv[1][mt][0] * wb0 + qv[2][mt][0] * wc0;
                x01 += qv[0][mt][0] * wa1 + qv[1][mt][0] * wb1 + qv[2][mt][0] * wc1;
                x10 += qv[0][mt][1] * wa0 + qv[1][mt][1] * wb0 + qv[2][mt][1] * wc0;
                x11 += qv[0][mt][1] * wa1 + qv[1][mt][1] * wb1 + qv[2][mt][1] * wc1;
            }
            x00 = fmaxf(x00, 0.f); x01 = fmaxf(x01, 0.f);
            x10 = fmaxf(x10, 0.f); x11 = fmaxf(x11, 0.f);
            sts32(sb + OFF_AH + m_lo * SA + n0 * 2, packh2(x00, x01));
            sts32(sb + OFF_AH + (m_lo + 8) * SA + n0 * 2, packh2(x10, x11));
            acc[mt][nt][0] = 0.f; acc[mt][nt][1] = 0.f;
            acc[mt][nt][2] = 0.f; acc[mt][nt][3] = 0.f;
        }
    }
}

// ---------------- main persistent kernel ------------------------------------
__global__ void __launch_bounds__(THREADS, 1)
interpnet_mma(const float* __restrict__ pos_source,
              const float* __restrict__ pos_target,
              const int*   __restrict__ row,
              const int*   __restrict__ col,
              const float* __restrict__ W_in, const float* __restrict__ b_in,
              const float* __restrict__ b1,  const float* __restrict__ b2,
              const float* __restrict__ W_out, const float* __restrict__ b_out,
              float* __restrict__ out, int E, int ntiles)
{
    extern __shared__ unsigned char sm[];
    const uint32_t sb = smem_u32(sm);

    const int tid  = threadIdx.x;
    const int lane = tid & 31;
    const int wid  = tid >> 5;
    const int m_base = (wid >> 2) * 64;
    const int n_base = (wid & 3) * 64;

    // ---- one-time consts ----
    for (int i = tid; i < 768; i += THREADS) {
        int l = i >> 8, n = i & 255;
        float v = (l == 0) ? b_in[n] : ((l == 1) ? b1[n] : b2[n]);
        stsf(sb + OFF_BIAS + i * 4, v);
    }
    for (int i = tid; i < 768; i += THREADS) {
        int d = i >> 8, n = i & 255;
        stsf(sb + OFF_WP + i * 4, W_in[(256 + d) * 256 + n]);
    }
    if (tid < 256) stsf(sb + OFF_WOUT + tid * 4, W_out[tid * 2]);

    const int t0 = blockIdx.x;
    if (t0 < ntiles) {
        const unsigned char* src = g_wpack + tid * 16;
        uint32_t dst = sb + OFF_W + tid * 16;
        #pragma unroll
        for (int i = 0; i < 10; i++) cp16(dst + i * 4096, src + i * 4096);
        CP_COMMIT();
        src += CH; dst += CH;
        #pragma unroll
        for (int i = 0; i < 10; i++) cp16(dst + i * 4096, src + i * 4096);
        CP_COMMIT();
        gather_tile(sb, tid, t0, E, col);
        pos_tile(sb, tid, t0, E, row, col, pos_target, pos_source);
    }

    const uint32_t aH = sb + OFF_AH + (m_base + (lane & 15)) * SA + ((lane >> 4) << 4);
    const uint32_t bB = sb + OFF_W + (n_base + (lane >> 2)) * SW + (lane & 3) * 4;

    #pragma unroll 1
    for (int t = t0; t < ntiles; t += gridDim.x) {
        const bool last = (t + (int)gridDim.x >= ntiles);

        float acc[4][8][4];
        #pragma unroll
        for (int mt = 0; mt < 4; mt++)
            #pragma unroll
            for (int nt = 0; nt < 8; nt++)
                #pragma unroll
                for (int q = 0; q < 4; q++) acc[mt][nt][q] = 0.f;

        #pragma unroll 1
        for (int g = 0; g < NG; g++) {
            const int l = g >> 3, c = g & 7, buf = g & 1;
            const uint32_t ka0 = (uint32_t)(c * KC) * 2;

            uint32_t ah0[4][4];
            if (c) {   // within layer: A stable, hoist frags above the wait
                #pragma unroll
                for (int mt = 0; mt < 4; mt++)
                    LDSM_X4(ah0[mt], aH + mt * 16 * SA + ka0);
            }
            if (g == 0) asm volatile("cp.async.wait_group 0;" ::: "memory");
            else        asm volatile("cp.async.wait_group 1;" ::: "memory");
            __syncthreads();
            if (!c) {
                #pragma unroll
                for (int mt = 0; mt < 4; mt++)
                    LDSM_X4(ah0[mt], aH + mt * 16 * SA + ka0);
            }

            const uint32_t wb = bB + buf * CH;
            // ks = 0
            #pragma unroll
            for (int nt = 0; nt < 8; nt++) {
                uint32_t o = wb + nt * 8 * SW;
                uint32_t bh0 = lds32(o),         bh1 = lds32(o + 16);
                uint32_t bl0 = lds32(o + 20480), bl1 = lds32(o + 20480 + 16);
                #pragma unroll
                for (int mt = 0; mt < 4; mt++) {
                    MMAF16(acc[mt][nt], ah0[mt], bh0, bh1);
                    MMAF16(acc[mt][nt], ah0[mt], bl0, bl1);
                }
            }
            // ks = 1
            {
                uint32_t ah1[4][4];
                const uint32_t ka1 = ka0 + 32;
                #pragma unroll
                for (int mt = 0; mt < 4; mt++)
                    LDSM_X4(ah1[mt], aH + mt * 16 * SA + ka1);
                #pragma unroll
                for (int nt = 0; nt < 8; nt++) {
                    uint32_t o = wb + nt * 8 * SW + 32;
                    uint32_t bh0 = lds32(o),         bh1 = lds32(o + 16);
                    uint32_t bl0 = lds32(o + 20480), bl1 = lds32(o + 20480 + 16);
                    #pragma unroll
                    for (int mt = 0; mt < 4; mt++) {
                        MMAF16(acc[mt][nt], ah1[mt], bh0, bh1);
                        MMAF16(acc[mt][nt], ah1[mt], bl0, bl1);
                    }
                }
            }
            __syncthreads();

            // stream next chunk (wraps into next tile's chunks 0,1)
            int cn = g + 2;
            bool issue = true;
            if (cn >= NG) { cn -= NG; issue = !last; }
            if (issue) {
                const unsigned char* csrc = g_wpack + (size_t)cn * CH + tid * 16;
                uint32_t cdst = sb + OFF_W + buf * CH + tid * 16;
                #pragma unroll
                for (int i = 0; i < 10; i++) cp16(cdst + i * 4096, csrc + i * 4096);
                CP_COMMIT();
            }

            if (c == 7 && l < 2) epilogue01(sb, l, lane, m_base, n_base, acc);
        }

        // ---- tile boundary: overlap next-tile gather with final epilogue ----
        const int t2 = t + (int)gridDim.x;
        if (t2 < ntiles) {
            gather_tile(sb, tid, t2, E, col);
            pos_tile(sb, tid, t2, E, row, col, pos_target, pos_source);
        }

        // layer-2 epilogue: project to W_out[:,0]
        float sfin[4][2] = {{0.f,0.f},{0.f,0.f},{0.f,0.f},{0.f,0.f}};
        #pragma unroll
        for (int nt = 0; nt < 8; nt++) {
            const int n0 = n_base + nt * 8 + (lane & 3) * 2;
            float wo0 = ldsf(sb + OFF_WOUT + n0 * 4);
            float wo1 = ldsf(sb + OFF_WOUT + (n0 + 1) * 4);
            float bi0 = ldsf(sb + OFF_BIAS + (512 + n0) * 4);
            float bi1 = ldsf(sb + OFF_BIAS + (512 + n0 + 1) * 4);
            #pragma unroll
            for (int mt = 0; mt < 4; mt++) {
                sfin[mt][0] += (acc[mt][nt][0] * WINV + bi0) * wo0
                             + (acc[mt][nt][1] * WINV + bi1) * wo1;
                sfin[mt][1] += (acc[mt][nt][2] * WINV + bi0) * wo0
                             + (acc[mt][nt][3] * WINV + bi1) * wo1;
            }
        }
        #pragma unroll
        for (int mt = 0; mt < 4; mt++) {
            float s0 = sfin[mt][0], s1 = sfin[mt][1];
            s0 += __shfl_xor_sync(0xffffffffu, s0, 1);
            s0 += __shfl_xor_sync(0xffffffffu, s0, 2);
            s1 += __shfl_xor_sync(0xffffffffu, s1, 1);
            s1 += __shfl_xor_sync(0xffffffffu, s1, 2);
            if ((lane & 3) == 0) {
                int m_lo = m_base + mt * 16 + (lane >> 2);
                stsf(sb + OFF_RED + (m_lo * 4 + (wid & 3)) * 4, s0);
                stsf(sb + OFF_RED + ((m_lo + 8) * 4 + (wid & 3)) * 4, s1);
            }
        }
        __syncthreads();
        if (tid < TILE_M) {
            float s = ldsf(sb + OFF_RED + (tid * 4 + 0) * 4)
                    + ldsf(sb + OFF_RED + (tid * 4 + 1) * 4)
                    + ldsf(sb + OFF_RED + (tid * 4 + 2) * 4)
                    + ldsf(sb + OFF_RED + (tid * 4 + 3) * 4);
            int e = t * TILE_M + tid;
            if (e < E) out[e] = s + __ldg(b_out);
        }
    }
}

// ---------------- launch -----------------------------------------------------
extern "C" void kernel_launch(void* const* d_in, const int* in_sizes, int n_in,
                              void* d_out, int out_size)
{
    const float* pos_source = (const float*)d_in[0];
    const float* pos_target = (const float*)d_in[1];
    const float* latents    = (const float*)d_in[2];
    const int*   row        = (const int*)  d_in[3];
    const int*   col        = (const int*)  d_in[4];
    const float* W_in  = (const float*)d_in[5];
    const float* b_in  = (const float*)d_in[6];
    const float* W1    = (const float*)d_in[7];
    const float* b1    = (const float*)d_in[8];
    const float* W2    = (const float*)d_in[9];
    const float* b2    = (const float*)d_in[10];
    const float* W_out = (const float*)d_in[11];
    const float* b_out = (const float*)d_in[12];
    float* out = (float*)d_out;

    const int E = in_sizes[3];
    int nrows = in_sizes[2] / 256;
    if (nrows > NSRC_MAX) nrows = NSRC_MAX;

    prep_weights<<<(NG * 256 * 16 + 255) / 256, 256>>>(W_in, W1, W2);
    prep_latents<<<(int)(((long)nrows * 64 + 255) / 256), 256>>>(latents, nrows);

    int numSMs = 148;
    cudaDeviceGetAttribute(&numSMs, cudaDevAttrMultiProcessorCount, 0);

    const int ntiles = (E + TILE_M - 1) / TILE_M;
    int grid = numSMs < ntiles ? numSMs : ntiles;

    cudaFuncSetAttribute(interpnet_mma,
                         cudaFuncAttributeMaxDynamicSharedMemorySize, SMEM_TOTAL);
    interpnet_mma<<<grid, THREADS, SMEM_TOTAL>>>(
        pos_source, pos_target, row, col,
        W_in, b_in, b1, b2, W_out, b_out, out, E, ntiles);
}